// round 1
// baseline (speedup 1.0000x reference)
#include <cuda_runtime.h>
#include <cstdint>

// Problem constants
#define B_    2
#define N_    1280
#define KNBR  48
#define CNODE 384
#define CEDGE 128
#define CBIAS 192
#define HID   512
#define COUT  128
#define M_    (B_*N_*KNBR)      // 122880 rows
#define BN_ROWS (B_*N_)         // 2560

// Scratch (device globals; allocation-free rule)
__device__ float g_n[BN_ROWS*CBIAS];            // ~2 MB
__device__ float g_X[(size_t)M_*HID];           // 252 MB  (X, later H2+X in-place)
__device__ float g_H[(size_t)M_*HID];           // 252 MB  (H1)

__device__ __forceinline__ unsigned f2tf32(float x){
    unsigned r; asm("cvt.rna.tf32.f32 %0, %1;" : "=r"(r) : "f"(x)); return r;
}

__device__ __forceinline__ void mma_tf32(float* d, const unsigned* a, const unsigned* b){
    asm volatile(
        "mma.sync.aligned.m16n8k8.row.col.f32.tf32.tf32.f32 "
        "{%0,%1,%2,%3},{%4,%5,%6,%7},{%8,%9},{%0,%1,%2,%3};\n"
        : "+f"(d[0]), "+f"(d[1]), "+f"(d[2]), "+f"(d[3])
        : "r"(a[0]), "r"(a[1]), "r"(a[2]), "r"(a[3]), "r"(b[0]), "r"(b[1]));
}

// ---------------------------------------------------------------------------
// Kernel 1: n = node_emb @ Wi + bi   [2560, 384] @ [384, 192]  (exact fp32)
// block = 16 rows, 192 threads (one per output col)
// ---------------------------------------------------------------------------
__global__ void node_proj_kernel(const float* __restrict__ node,
                                 const float* __restrict__ Wi,
                                 const float* __restrict__ bi,
                                 float* __restrict__ nout)
{
    __shared__ float4 sa[16*96];     // 16 rows x 384 cols
    const int r0 = blockIdx.x * 16;
    const float4* node4 = (const float4*)node + (size_t)r0 * 96;
    #pragma unroll
    for (int i = 0; i < 8; i++){
        int f = threadIdx.x + i*192;
        sa[f] = node4[f];
    }
    __syncthreads();

    const int c = threadIdx.x;       // 0..191
    float acc[16];
    #pragma unroll
    for (int r = 0; r < 16; r++) acc[r] = 0.f;

    for (int kt = 0; kt < 96; kt++){
        float w0 = Wi[(kt*4+0)*CBIAS + c];
        float w1 = Wi[(kt*4+1)*CBIAS + c];
        float w2 = Wi[(kt*4+2)*CBIAS + c];
        float w3 = Wi[(kt*4+3)*CBIAS + c];
        #pragma unroll
        for (int r = 0; r < 16; r++){
            float4 a = sa[r*96 + kt];        // broadcast across warp
            acc[r] += a.x*w0 + a.y*w1 + a.z*w2 + a.w*w3;
        }
    }
    float bb = bi[c];
    #pragma unroll
    for (int r = 0; r < 16; r++)
        nout[(size_t)(r0+r)*CBIAS + c] = acc[r] + bb;
}

// ---------------------------------------------------------------------------
// Kernel 2: build X[m, 0:512] = concat(edge_emb[m], n[b,i], n[b, E_idx[m]])
// one thread per float4 of X
// ---------------------------------------------------------------------------
__global__ void build_x_kernel(const float* __restrict__ edge,
                               const float* __restrict__ nproj,
                               const int*   __restrict__ eidx,
                               float*       __restrict__ X)
{
    const int f  = blockIdx.x * 256 + threadIdx.x;   // 0 .. M*128-1
    const int m  = f >> 7;
    const int c4 = f & 127;
    const float4* e4 = (const float4*)edge;
    const float4* n4 = (const float4*)nproj;
    float4 v;
    if (c4 < 32){
        v = e4[(size_t)m*32 + c4];
    } else if (c4 < 80){
        int bi_ = m / KNBR;                          // b*N + i
        v = n4[(size_t)bi_*48 + (c4 - 32)];
    } else {
        int bi_ = m / KNBR;
        int b   = bi_ / N_;
        int j   = eidx[m];
        v = n4[((size_t)b*N_ + j)*48 + (c4 - 80)];
    }
    ((float4*)X)[f] = v;
}

// ---------------------------------------------------------------------------
// Fused tiled TF32 GEMM: Out = epi(A[M,512] @ Wm[512 or 128 wide] + bias)
// BM=128, BN=128, BK=32, 512 threads, warps 4(M) x 4(N), warp tile 32x32.
// EPI: 0 = relu, 1 = relu + residual, 2 = bias + LayerNorm(128) (ldO=128)
// ---------------------------------------------------------------------------
enum { EPI_RELU = 0, EPI_RELU_RES = 1, EPI_LN = 2 };

template<int EPI>
__global__ __launch_bounds__(512)
void gemm_kernel(const float* __restrict__ A,
                 const float* __restrict__ Wm,
                 const float* __restrict__ bias,
                 const float* Res,                 // no restrict: may alias Out
                 const float* __restrict__ gamma,
                 const float* __restrict__ beta,
                 float* Out,                       // no restrict: may alias Res
                 int ldB, int ldO)
{
    __shared__ unsigned As[128*36];   // A tile [m][k], stride 36 -> conflict-free frags
    __shared__ unsigned Bs[32*136];   // B tile [k][n], stride 136 -> conflict-free frags
    __shared__ float s_bias[128];
    __shared__ float s_gamma[128], s_beta[128];
    __shared__ float s_sum[4][128], s_sq[4][128];  // per-warp_n deterministic partials

    const int t    = threadIdx.x;
    const int wid  = t >> 5, lane = t & 31;
    const int wm   = (wid & 3) * 32;     // warp M offset
    const int wni  = wid >> 2;           // warp N index 0..3
    const int wn   = wni * 32;
    const int g    = lane >> 2, tig = lane & 3;
    const int m0   = blockIdx.y * 128, n0 = blockIdx.x * 128;

    if (t < 128){
        s_bias[t] = bias[n0 + t];
        if (EPI == EPI_LN){ s_gamma[t] = gamma[t]; s_beta[t] = beta[t]; }
    }

    float acc[2][4][4];
    #pragma unroll
    for (int mt = 0; mt < 2; mt++)
        #pragma unroll
        for (int nt = 0; nt < 4; nt++)
            #pragma unroll
            for (int r = 0; r < 4; r++) acc[mt][nt][r] = 0.f;

    // global load base pointers (per-thread)
    const float* Aptr = A  + (size_t)(m0 + (t >> 3)) * HID + (t & 7) * 4;
    const float* Bptr = Wm + (size_t)(t >> 5) * ldB + n0 + (t & 31) * 4;
    unsigned* asd0 = As + (t >> 3) * 36 + (t & 7) * 4;
    unsigned* asd1 = asd0 + 64 * 36;
    unsigned* bsd0 = Bs + (t >> 5) * 136 + (t & 31) * 4;
    unsigned* bsd1 = bsd0 + 16 * 136;

    // prologue: tile 0
    float4 ra0 = *(const float4*)(Aptr);
    float4 ra1 = *(const float4*)(Aptr + 64 * HID);
    float4 rb0 = *(const float4*)(Bptr);
    float4 rb1 = *(const float4*)(Bptr + 16 * ldB);
    {
        uint4 u;
        u.x=f2tf32(ra0.x); u.y=f2tf32(ra0.y); u.z=f2tf32(ra0.z); u.w=f2tf32(ra0.w);
        *(uint4*)asd0 = u;
        u.x=f2tf32(ra1.x); u.y=f2tf32(ra1.y); u.z=f2tf32(ra1.z); u.w=f2tf32(ra1.w);
        *(uint4*)asd1 = u;
        u.x=f2tf32(rb0.x); u.y=f2tf32(rb0.y); u.z=f2tf32(rb0.z); u.w=f2tf32(rb0.w);
        *(uint4*)bsd0 = u;
        u.x=f2tf32(rb1.x); u.y=f2tf32(rb1.y); u.z=f2tf32(rb1.z); u.w=f2tf32(rb1.w);
        *(uint4*)bsd1 = u;
    }
    __syncthreads();

    for (int kt = 0; kt < 16; kt++){
        // prefetch next tile into registers (overlaps with compute)
        if (kt < 15){
            int kb = (kt + 1) * 32;
            ra0 = *(const float4*)(Aptr + kb);
            ra1 = *(const float4*)(Aptr + 64 * HID + kb);
            rb0 = *(const float4*)(Bptr + (size_t)kb * ldB);
            rb1 = *(const float4*)(Bptr + (size_t)(kb + 16) * ldB);
        }
        // compute current tile
        #pragma unroll
        for (int kk = 0; kk < 4; kk++){
            const int k0 = kk * 8;
            unsigned af[2][4], bf[4][2];
            #pragma unroll
            for (int mt = 0; mt < 2; mt++){
                int r = wm + mt*16 + g;
                af[mt][0] = As[(r    )*36 + k0 + tig    ];
                af[mt][1] = As[(r + 8)*36 + k0 + tig    ];
                af[mt][2] = As[(r    )*36 + k0 + tig + 4];
                af[mt][3] = As[(r + 8)*36 + k0 + tig + 4];
            }
            #pragma unroll
            for (int nt = 0; nt < 4; nt++){
                int c = wn + nt*8 + g;
                bf[nt][0] = Bs[(k0 + tig    )*136 + c];
                bf[nt][1] = Bs[(k0 + tig + 4)*136 + c];
            }
            #pragma unroll
            for (int mt = 0; mt < 2; mt++)
                #pragma unroll
                for (int nt = 0; nt < 4; nt++)
                    mma_tf32(acc[mt][nt], af[mt], bf[nt]);
        }
        __syncthreads();
        if (kt < 15){
            uint4 u;
            u.x=f2tf32(ra0.x); u.y=f2tf32(ra0.y); u.z=f2tf32(ra0.z); u.w=f2tf32(ra0.w);
            *(uint4*)asd0 = u;
            u.x=f2tf32(ra1.x); u.y=f2tf32(ra1.y); u.z=f2tf32(ra1.z); u.w=f2tf32(ra1.w);
            *(uint4*)asd1 = u;
            u.x=f2tf32(rb0.x); u.y=f2tf32(rb0.y); u.z=f2tf32(rb0.z); u.w=f2tf32(rb0.w);
            *(uint4*)bsd0 = u;
            u.x=f2tf32(rb1.x); u.y=f2tf32(rb1.y); u.z=f2tf32(rb1.z); u.w=f2tf32(rb1.w);
            *(uint4*)bsd1 = u;
            __syncthreads();
        }
    }

    if (EPI != EPI_LN){
        // bias + relu (+ residual), sector-perfect float2 stores
        #pragma unroll
        for (int mt = 0; mt < 2; mt++)
            #pragma unroll
            for (int hi = 0; hi < 2; hi++){
                int r = m0 + wm + mt*16 + g + hi*8;
                #pragma unroll
                for (int nt = 0; nt < 4; nt++){
                    int cl = wn + nt*8 + tig*2;
                    float v0 = acc[mt][nt][hi*2    ] + s_bias[cl    ];
                    float v1 = acc[mt][nt][hi*2 + 1] + s_bias[cl + 1];
                    v0 = fmaxf(v0, 0.f); v1 = fmaxf(v1, 0.f);
                    if (EPI == EPI_RELU_RES){
                        float2 x = *(const float2*)(Res + (size_t)r*HID + n0 + cl);
                        v0 += x.x; v1 += x.y;
                    }
                    *(float2*)(Out + (size_t)r*ldO + n0 + cl) = make_float2(v0, v1);
                }
            }
    } else {
        // bias, then fused LayerNorm over the 128 output channels (n0 == 0)
        #pragma unroll
        for (int mt = 0; mt < 2; mt++)
            #pragma unroll
            for (int nt = 0; nt < 4; nt++){
                int cl = wn + nt*8 + tig*2;
                acc[mt][nt][0] += s_bias[cl];     acc[mt][nt][1] += s_bias[cl+1];
                acc[mt][nt][2] += s_bias[cl];     acc[mt][nt][3] += s_bias[cl+1];
            }
        // per-(row, warp_n) partial sums: reduce over quad (tig) with shfl
        #pragma unroll
        for (int mt = 0; mt < 2; mt++)
            #pragma unroll
            for (int hi = 0; hi < 2; hi++){
                float s = 0.f, q = 0.f;
                #pragma unroll
                for (int nt = 0; nt < 4; nt++){
                    float v0 = acc[mt][nt][hi*2], v1 = acc[mt][nt][hi*2+1];
                    s += v0 + v1; q += v0*v0 + v1*v1;
                }
                s += __shfl_xor_sync(0xffffffffu, s, 1);
                s += __shfl_xor_sync(0xffffffffu, s, 2);
                q += __shfl_xor_sync(0xffffffffu, q, 1);
                q += __shfl_xor_sync(0xffffffffu, q, 2);
                if (tig == 0){
                    int rl = wm + mt*16 + g + hi*8;
                    s_sum[wni][rl] = s;
                    s_sq [wni][rl] = q;
                }
            }
        __syncthreads();
        #pragma unroll
        for (int mt = 0; mt < 2; mt++)
            #pragma unroll
            for (int hi = 0; hi < 2; hi++){
                int rl = wm + mt*16 + g + hi*8;
                float s = s_sum[0][rl] + s_sum[1][rl] + s_sum[2][rl] + s_sum[3][rl];
                float q = s_sq [0][rl] + s_sq [1][rl] + s_sq [2][rl] + s_sq [3][rl];
                float mean = s * (1.f/128.f);
                float var  = q * (1.f/128.f) - mean*mean;
                float rstd = rsqrtf(var + 1e-5f);
                size_t rbase = (size_t)(m0 + rl) * COUT;
                #pragma unroll
                for (int nt = 0; nt < 4; nt++){
                    int cl = wn + nt*8 + tig*2;
                    float v0 = (acc[mt][nt][hi*2    ] - mean)*rstd*s_gamma[cl    ] + s_beta[cl    ];
                    float v1 = (acc[mt][nt][hi*2 + 1] - mean)*rstd*s_gamma[cl + 1] + s_beta[cl + 1];
                    *(float2*)(Out + rbase + cl) = make_float2(v0, v1);
                }
            }
    }
}

// ---------------------------------------------------------------------------
extern "C" void kernel_launch(void* const* d_in, const int* in_sizes, int n_in,
                              void* d_out, int out_size)
{
    const float* node  = (const float*)d_in[0];
    const float* edge  = (const float*)d_in[1];
    const int*   eidx  = (const int*)  d_in[2];
    const float* Wi    = (const float*)d_in[3];
    const float* bi    = (const float*)d_in[4];
    const float* W1    = (const float*)d_in[5];
    const float* b1    = (const float*)d_in[6];
    const float* W2    = (const float*)d_in[7];
    const float* b2    = (const float*)d_in[8];
    const float* Wf    = (const float*)d_in[9];
    const float* bf    = (const float*)d_in[10];
    const float* gamma = (const float*)d_in[11];
    const float* beta  = (const float*)d_in[12];
    float* out = (float*)d_out;

    void *pn, *px, *ph;
    cudaGetSymbolAddress(&pn, g_n);
    cudaGetSymbolAddress(&px, g_X);
    cudaGetSymbolAddress(&ph, g_H);
    float* gn = (float*)pn;
    float* gX = (float*)px;
    float* gH = (float*)ph;

    // 1. node projection (exact fp32)
    node_proj_kernel<<<BN_ROWS/16, 192>>>(node, Wi, bi, gn);

    // 2. build X = concat(edge, self, nbr)
    build_x_kernel<<<(M_*128)/256, 256>>>(edge, gn, eidx, gX);

    // 3. H = relu(X @ W1 + b1)
    dim3 grid12(HID/128, M_/128);
    gemm_kernel<EPI_RELU><<<grid12, 512>>>(gX, W1, b1, nullptr, nullptr, nullptr, gH, HID, HID);

    // 4. X <- relu(H @ W2 + b2) + X   (in-place residual)
    gemm_kernel<EPI_RELU_RES><<<grid12, 512>>>(gH, W2, b2, gX, nullptr, nullptr, gX, HID, HID);

    // 5. out = LayerNorm((H2+X) @ Wf + bf) * gamma + beta
    dim3 grid3(1, M_/128);
    gemm_kernel<EPI_LN><<<grid3, 512>>>(gX, Wf, bf, nullptr, gamma, beta, out, COUT, COUT);
}

// round 2
// speedup vs baseline: 1.7075x; 1.7075x over previous
#include <cuda_runtime.h>
#include <cstdint>

// Problem constants
#define B_    2
#define N_    1280
#define KNBR  48
#define CNODE 384
#define CEDGE 128
#define CBIAS 192
#define HID   512
#define COUT  128
#define M_    (B_*N_*KNBR)      // 122880 rows
#define BN_ROWS (B_*N_)         // 2560

// Scratch (device globals; allocation-free rule)
__device__ float g_n[BN_ROWS*CBIAS];            // ~2 MB
__device__ float g_X[(size_t)M_*HID];           // 252 MB  (X, later H2+X in-place)
__device__ float g_H[(size_t)M_*HID];           // 252 MB  (H1)
__device__ float g_W1r[HID*HID];                // tf32-rounded weights
__device__ float g_W2r[HID*HID];
__device__ float g_Wfr[HID*COUT];

__device__ __forceinline__ unsigned f2tf32(float x){
    unsigned r; asm("cvt.rna.tf32.f32 %0, %1;" : "=r"(r) : "f"(x)); return r;
}
__device__ __forceinline__ float tf32r(float x){ return __uint_as_float(f2tf32(x)); }

__device__ __forceinline__ void mma_tf32(float* d, const unsigned* a, const unsigned* b){
    asm volatile(
        "mma.sync.aligned.m16n8k8.row.col.f32.tf32.tf32.f32 "
        "{%0,%1,%2,%3},{%4,%5,%6,%7},{%8,%9},{%0,%1,%2,%3};\n"
        : "+f"(d[0]), "+f"(d[1]), "+f"(d[2]), "+f"(d[3])
        : "r"(a[0]), "r"(a[1]), "r"(a[2]), "r"(a[3]), "r"(b[0]), "r"(b[1]));
}

__device__ __forceinline__ uint32_t smem_u32(const void* p){
    return (uint32_t)__cvta_generic_to_shared(p);
}
__device__ __forceinline__ void cpasync16(uint32_t dst, const void* src){
    asm volatile("cp.async.cg.shared.global [%0], [%1], 16;\n" :: "r"(dst), "l"(src));
}
#define CP_COMMIT asm volatile("cp.async.commit_group;\n" ::: "memory")
#define CP_WAIT0  asm volatile("cp.async.wait_group 0;\n" ::: "memory")
#define CP_WAIT1  asm volatile("cp.async.wait_group 1;\n" ::: "memory")

// ---------------------------------------------------------------------------
// Kernel 0: round weights to tf32 once (cheap, ~1MB)
// ---------------------------------------------------------------------------
__global__ void round_tf32_kernel(const float* __restrict__ in, float* __restrict__ out, int n){
    int i = blockIdx.x * 256 + threadIdx.x;
    if (i < n) out[i] = tf32r(in[i]);
}

// ---------------------------------------------------------------------------
// Kernel 1: n = node_emb @ Wi + bi   [2560, 384] @ [384, 192]  (exact fp32)
// ---------------------------------------------------------------------------
__global__ void node_proj_kernel(const float* __restrict__ node,
                                 const float* __restrict__ Wi,
                                 const float* __restrict__ bi,
                                 float* __restrict__ nout)
{
    __shared__ float4 sa[16*96];
    const int r0 = blockIdx.x * 16;
    const float4* node4 = (const float4*)node + (size_t)r0 * 96;
    #pragma unroll
    for (int i = 0; i < 8; i++){
        int f = threadIdx.x + i*192;
        sa[f] = node4[f];
    }
    __syncthreads();

    const int c = threadIdx.x;       // 0..191
    float acc[16];
    #pragma unroll
    for (int r = 0; r < 16; r++) acc[r] = 0.f;

    for (int kt = 0; kt < 96; kt++){
        float w0 = Wi[(kt*4+0)*CBIAS + c];
        float w1 = Wi[(kt*4+1)*CBIAS + c];
        float w2 = Wi[(kt*4+2)*CBIAS + c];
        float w3 = Wi[(kt*4+3)*CBIAS + c];
        #pragma unroll
        for (int r = 0; r < 16; r++){
            float4 a = sa[r*96 + kt];
            acc[r] += a.x*w0 + a.y*w1 + a.z*w2 + a.w*w3;
        }
    }
    float bb = bi[c];
    #pragma unroll
    for (int r = 0; r < 16; r++)
        nout[(size_t)(r0+r)*CBIAS + c] = acc[r] + bb;
}

// ---------------------------------------------------------------------------
// Kernel 2: build X = concat(edge, self, nbr), tf32-rounded
// ---------------------------------------------------------------------------
__global__ void build_x_kernel(const float* __restrict__ edge,
                               const float* __restrict__ nproj,
                               const int*   __restrict__ eidx,
                               float*       __restrict__ X)
{
    const int f  = blockIdx.x * 256 + threadIdx.x;   // 0 .. M*128-1
    const int m  = f >> 7;
    const int c4 = f & 127;
    const float4* e4 = (const float4*)edge;
    const float4* n4 = (const float4*)nproj;
    float4 v;
    if (c4 < 32){
        v = e4[(size_t)m*32 + c4];
    } else if (c4 < 80){
        int bi_ = m / KNBR;
        v = n4[(size_t)bi_*48 + (c4 - 32)];
    } else {
        int bi_ = m / KNBR;
        int b   = bi_ / N_;
        int j   = eidx[m];
        v = n4[((size_t)b*N_ + j)*48 + (c4 - 80)];
    }
    v.x = tf32r(v.x); v.y = tf32r(v.y); v.z = tf32r(v.z); v.w = tf32r(v.w);
    ((float4*)X)[f] = v;
}

// ---------------------------------------------------------------------------
// Tiled TF32 GEMM with cp.async double-buffered smem.
// BM=128, BN=128, BK=32, 512 threads, warps 4(M) x 4(N), warp tile 32x32.
// All operands pre-rounded to tf32. 2 CTAs/SM via launch_bounds.
// EPI: 0 = relu (tf32-rounded store), 1 = relu + residual (rounded),
//      2 = bias + LayerNorm(128), exact fp32 store
// ---------------------------------------------------------------------------
enum { EPI_RELU = 0, EPI_RELU_RES = 1, EPI_LN = 2 };

#define AS_STRIDE 36
#define BS_STRIDE 136
#define AS_TILE   (128*AS_STRIDE)    // floats per stage
#define BS_TILE   (32*BS_STRIDE)

template<int EPI>
__global__ __launch_bounds__(512, 2)
void gemm_kernel(const float* __restrict__ A,
                 const float* __restrict__ Wm,
                 const float* __restrict__ bias,
                 const float* Res,                 // may alias Out
                 const float* __restrict__ gamma,
                 const float* __restrict__ beta,
                 float* Out,
                 int ldB, int ldO)
{
    extern __shared__ float smem[];
    float* As     = smem;                       // 2 stages
    float* Bs     = As + 2*AS_TILE;
    float* s_bias = Bs + 2*BS_TILE;             // 128
    float* s_gamma= s_bias + 128;               // 128
    float* s_beta = s_gamma + 128;              // 128
    float* s_sum  = s_beta + 128;               // 4*128
    float* s_sq   = s_sum + 512;                // 4*128

    const int t    = threadIdx.x;
    const int wid  = t >> 5, lane = t & 31;
    const int wm   = (wid & 3) * 32;
    const int wni  = wid >> 2;
    const int wn   = wni * 32;
    const int g    = lane >> 2, tig = lane & 3;
    const int m0   = blockIdx.y * 128, n0 = blockIdx.x * 128;

    if (t < 128){
        s_bias[t] = bias[n0 + t];
        if (EPI == EPI_LN){ s_gamma[t] = gamma[t]; s_beta[t] = beta[t]; }
    }

    float acc[2][4][4];
    #pragma unroll
    for (int mt = 0; mt < 2; mt++)
        #pragma unroll
        for (int nt = 0; nt < 4; nt++)
            #pragma unroll
            for (int r = 0; r < 4; r++) acc[mt][nt][r] = 0.f;

    // per-thread load coordinates
    const float* Ag = A  + (size_t)(m0 + (t >> 3)) * HID + (t & 7) * 4;   // rows t>>3, +64
    const float* Bg = Wm + (size_t)(t >> 5) * ldB + n0 + (t & 31) * 4;    // k rows t>>5, +16
    const uint32_t aS = smem_u32(As) + (((t >> 3) * AS_STRIDE + (t & 7) * 4) << 2);
    const uint32_t bS = smem_u32(Bs) + (((t >> 5) * BS_STRIDE + (t & 31) * 4) << 2);
    const uint32_t aStage = AS_TILE << 2, bStage = BS_TILE << 2;

    // prologue: stage 0
    cpasync16(aS,                    Ag);
    cpasync16(aS + (64*AS_STRIDE<<2), Ag + 64*HID);
    cpasync16(bS,                    Bg);
    cpasync16(bS + (16*BS_STRIDE<<2), Bg + (size_t)16*ldB);
    CP_COMMIT;

    for (int kt = 0; kt < 16; kt++){
        const int cur = kt & 1;
        if (kt < 15){
            const int kb = (kt + 1) * 32;
            const uint32_t nb = (kt + 1) & 1;
            cpasync16(aS + nb*aStage,                    Ag + kb);
            cpasync16(aS + nb*aStage + (64*AS_STRIDE<<2), Ag + 64*HID + kb);
            cpasync16(bS + nb*bStage,                    Bg + (size_t)kb*ldB);
            cpasync16(bS + nb*bStage + (16*BS_STRIDE<<2), Bg + (size_t)(kb+16)*ldB);
            CP_COMMIT;
            CP_WAIT1;                        // stage kt complete
        } else {
            CP_WAIT0;
        }
        __syncthreads();

        const float* Asf = As + cur * AS_TILE;
        const float* Bsf = Bs + cur * BS_TILE;
        #pragma unroll
        for (int kk = 0; kk < 4; kk++){
            const int k0 = kk * 8;
            unsigned af[2][4], bf[4][2];
            #pragma unroll
            for (int mt = 0; mt < 2; mt++){
                int r = wm + mt*16 + g;
                af[mt][0] = __float_as_uint(Asf[(r    )*AS_STRIDE + k0 + tig    ]);
                af[mt][1] = __float_as_uint(Asf[(r + 8)*AS_STRIDE + k0 + tig    ]);
                af[mt][2] = __float_as_uint(Asf[(r    )*AS_STRIDE + k0 + tig + 4]);
                af[mt][3] = __float_as_uint(Asf[(r + 8)*AS_STRIDE + k0 + tig + 4]);
            }
            #pragma unroll
            for (int nt = 0; nt < 4; nt++){
                int c = wn + nt*8 + g;
                bf[nt][0] = __float_as_uint(Bsf[(k0 + tig    )*BS_STRIDE + c]);
                bf[nt][1] = __float_as_uint(Bsf[(k0 + tig + 4)*BS_STRIDE + c]);
            }
            #pragma unroll
            for (int mt = 0; mt < 2; mt++)
                #pragma unroll
                for (int nt = 0; nt < 4; nt++)
                    mma_tf32(acc[mt][nt], af[mt], bf[nt]);
        }
        __syncthreads();
    }

    if (EPI != EPI_LN){
        #pragma unroll
        for (int mt = 0; mt < 2; mt++)
            #pragma unroll
            for (int hi = 0; hi < 2; hi++){
                int r = m0 + wm + mt*16 + g + hi*8;
                #pragma unroll
                for (int nt = 0; nt < 4; nt++){
                    int cl = wn + nt*8 + tig*2;
                    float v0 = acc[mt][nt][hi*2    ] + s_bias[cl    ];
                    float v1 = acc[mt][nt][hi*2 + 1] + s_bias[cl + 1];
                    v0 = fmaxf(v0, 0.f); v1 = fmaxf(v1, 0.f);
                    if (EPI == EPI_RELU_RES){
                        float2 x = *(const float2*)(Res + (size_t)r*HID + n0 + cl);
                        v0 += x.x; v1 += x.y;
                    }
                    // round for the next GEMM's tf32 consumption
                    v0 = tf32r(v0); v1 = tf32r(v1);
                    *(float2*)(Out + (size_t)r*ldO + n0 + cl) = make_float2(v0, v1);
                }
            }
    } else {
        // bias, then fused LayerNorm over 128 output channels (n0 == 0)
        #pragma unroll
        for (int mt = 0; mt < 2; mt++)
            #pragma unroll
            for (int nt = 0; nt < 4; nt++){
                int cl = wn + nt*8 + tig*2;
                acc[mt][nt][0] += s_bias[cl];     acc[mt][nt][1] += s_bias[cl+1];
                acc[mt][nt][2] += s_bias[cl];     acc[mt][nt][3] += s_bias[cl+1];
            }
        #pragma unroll
        for (int mt = 0; mt < 2; mt++)
            #pragma unroll
            for (int hi = 0; hi < 2; hi++){
                float s = 0.f, q = 0.f;
                #pragma unroll
                for (int nt = 0; nt < 4; nt++){
                    float v0 = acc[mt][nt][hi*2], v1 = acc[mt][nt][hi*2+1];
                    s += v0 + v1; q += v0*v0 + v1*v1;
                }
                s += __shfl_xor_sync(0xffffffffu, s, 1);
                s += __shfl_xor_sync(0xffffffffu, s, 2);
                q += __shfl_xor_sync(0xffffffffu, q, 1);
                q += __shfl_xor_sync(0xffffffffu, q, 2);
                if (tig == 0){
                    int rl = wm + mt*16 + g + hi*8;
                    s_sum[wni*128 + rl] = s;
                    s_sq [wni*128 + rl] = q;
                }
            }
        __syncthreads();
        #pragma unroll
        for (int mt = 0; mt < 2; mt++)
            #pragma unroll
            for (int hi = 0; hi < 2; hi++){
                int rl = wm + mt*16 + g + hi*8;
                float s = s_sum[0*128+rl] + s_sum[1*128+rl] + s_sum[2*128+rl] + s_sum[3*128+rl];
                float q = s_sq [0*128+rl] + s_sq [1*128+rl] + s_sq [2*128+rl] + s_sq [3*128+rl];
                float mean = s * (1.f/128.f);
                float var  = q * (1.f/128.f) - mean*mean;
                float rstd = rsqrtf(var + 1e-5f);
                size_t rbase = (size_t)(m0 + rl) * COUT;
                #pragma unroll
                for (int nt = 0; nt < 4; nt++){
                    int cl = wn + nt*8 + tig*2;
                    float v0 = (acc[mt][nt][hi*2    ] - mean)*rstd*s_gamma[cl    ] + s_beta[cl    ];
                    float v1 = (acc[mt][nt][hi*2 + 1] - mean)*rstd*s_gamma[cl + 1] + s_beta[cl + 1];
                    *(float2*)(Out + rbase + cl) = make_float2(v0, v1);
                }
            }
    }
}

// ---------------------------------------------------------------------------
extern "C" void kernel_launch(void* const* d_in, const int* in_sizes, int n_in,
                              void* d_out, int out_size)
{
    const float* node  = (const float*)d_in[0];
    const float* edge  = (const float*)d_in[1];
    const int*   eidx  = (const int*)  d_in[2];
    const float* Wi    = (const float*)d_in[3];
    const float* bi    = (const float*)d_in[4];
    const float* W1    = (const float*)d_in[5];
    const float* b1    = (const float*)d_in[6];
    const float* W2    = (const float*)d_in[7];
    const float* b2    = (const float*)d_in[8];
    const float* Wf    = (const float*)d_in[9];
    const float* bf    = (const float*)d_in[10];
    const float* gamma = (const float*)d_in[11];
    const float* beta  = (const float*)d_in[12];
    float* out = (float*)d_out;

    void *pn, *px, *ph, *pw1, *pw2, *pwf;
    cudaGetSymbolAddress(&pn,  g_n);
    cudaGetSymbolAddress(&px,  g_X);
    cudaGetSymbolAddress(&ph,  g_H);
    cudaGetSymbolAddress(&pw1, g_W1r);
    cudaGetSymbolAddress(&pw2, g_W2r);
    cudaGetSymbolAddress(&pwf, g_Wfr);
    float* gn  = (float*)pn;
    float* gX  = (float*)px;
    float* gH  = (float*)ph;
    float* W1r = (float*)pw1;
    float* W2r = (float*)pw2;
    float* Wfr = (float*)pwf;

    // opt in to >48KB dynamic smem (idempotent)
    const int smem_bytes = (2*AS_TILE + 2*BS_TILE + 128*3 + 1024) * 4;
    cudaFuncSetAttribute(gemm_kernel<EPI_RELU>,     cudaFuncAttributeMaxDynamicSharedMemorySize, smem_bytes);
    cudaFuncSetAttribute(gemm_kernel<EPI_RELU_RES>, cudaFuncAttributeMaxDynamicSharedMemorySize, smem_bytes);
    cudaFuncSetAttribute(gemm_kernel<EPI_LN>,       cudaFuncAttributeMaxDynamicSharedMemorySize, smem_bytes);

    // 0. pre-round weights to tf32
    round_tf32_kernel<<<(HID*HID+255)/256, 256>>>(W1, W1r, HID*HID);
    round_tf32_kernel<<<(HID*HID+255)/256, 256>>>(W2, W2r, HID*HID);
    round_tf32_kernel<<<(HID*COUT+255)/256, 256>>>(Wf, Wfr, HID*COUT);

    // 1. node projection (exact fp32)
    node_proj_kernel<<<BN_ROWS/16, 192>>>(node, Wi, bi, gn);

    // 2. build X = concat(edge, self, nbr), tf32-rounded
    build_x_kernel<<<(M_*128)/256, 256>>>(edge, gn, eidx, gX);

    // 3. H = relu(X @ W1 + b1)  (tf32-rounded store)
    dim3 grid12(HID/128, M_/128);
    gemm_kernel<EPI_RELU><<<grid12, 512, smem_bytes>>>(gX, W1r, b1, nullptr, nullptr, nullptr, gH, HID, HID);

    // 4. X <- relu(H @ W2 + b2) + X   (in-place residual, rounded)
    gemm_kernel<EPI_RELU_RES><<<grid12, 512, smem_bytes>>>(gH, W2r, b2, gX, nullptr, nullptr, gX, HID, HID);

    // 5. out = LayerNorm((H2+X) @ Wf + bf) * gamma + beta  (exact fp32 out)
    dim3 grid3(1, M_/128);
    gemm_kernel<EPI_LN><<<grid3, 512, smem_bytes>>>(gX, Wfr, bf, nullptr, gamma, beta, out, COUT, COUT);
}

// round 5
// speedup vs baseline: 1.7937x; 1.0505x over previous
#include <cuda_runtime.h>
#include <cstdint>

#define B_    2
#define N_    1280
#define KNBR  48
#define CBIAS 192
#define HID   512
#define COUT  128
#define M_    (B_*N_*KNBR)      // 122880
#define BN_ROWS (B_*N_)         // 2560

#define LDA    36               // padded smem row stride (floats)
#define TILEF  (128*LDA)        // floats per 128x32 tile
#define STAGEF (2*TILEF)        // A + B per stage
#define DYN_BYTES (2*STAGEF*4)  // 2 stages

// Scratch (device globals; allocation-free rule)
__device__ float g_n[BN_ROWS*CBIAS];
__device__ float g_X[(size_t)M_*HID];
__device__ float g_H[(size_t)M_*HID];
__device__ float g_W1t[HID*HID];     // [N][K] transposed + tf32-rounded
__device__ float g_W2t[HID*HID];
__device__ float g_Wft[COUT*HID];

__device__ __forceinline__ unsigned f2tf32(float x){
    unsigned r; asm("cvt.rna.tf32.f32 %0, %1;" : "=r"(r) : "f"(x)); return r;
}
__device__ __forceinline__ float tf32r(float x){ return __uint_as_float(f2tf32(x)); }
__device__ __forceinline__ uint32_t smem_u32(const void* p){
    return (uint32_t)__cvta_generic_to_shared(p);
}
__device__ __forceinline__ void cpasync16(uint32_t dst, const void* src){
    asm volatile("cp.async.cg.shared.global [%0], [%1], 16;\n" :: "r"(dst), "l"(src));
}
#define CP_COMMIT asm volatile("cp.async.commit_group;\n" ::: "memory")
#define CP_WAIT0  asm volatile("cp.async.wait_group 0;\n" ::: "memory")
#define CP_WAIT1  asm volatile("cp.async.wait_group 1;\n" ::: "memory")

__device__ __forceinline__ void mma_tf32(float* d, const unsigned* a, const unsigned* b){
    asm volatile(
        "mma.sync.aligned.m16n8k8.row.col.f32.tf32.tf32.f32 "
        "{%0,%1,%2,%3},{%4,%5,%6,%7},{%8,%9},{%0,%1,%2,%3};\n"
        : "+f"(d[0]), "+f"(d[1]), "+f"(d[2]), "+f"(d[3])
        : "r"(a[0]), "r"(a[1]), "r"(a[2]), "r"(a[3]), "r"(b[0]), "r"(b[1]));
}
__device__ __forceinline__ void ldsm4(unsigned* r, uint32_t addr){
    asm volatile("ldmatrix.sync.aligned.m8n8.x4.shared.b16 {%0,%1,%2,%3}, [%4];"
        : "=r"(r[0]), "=r"(r[1]), "=r"(r[2]), "=r"(r[3]) : "r"(addr));
}

// ---------------------------------------------------------------------------
// prep: dst[n*K+k] = tf32(src[k*N+n])   (transpose + round)
// ---------------------------------------------------------------------------
__global__ void transpose_round_kernel(const float* __restrict__ src,
                                       float* __restrict__ dst, int K, int N)
{
    __shared__ float tile[32][33];
    const int kb = blockIdx.x*32, nb = blockIdx.y*32;
    const int tx = threadIdx.x, ty = threadIdx.y;
    #pragma unroll
    for (int i = 0; i < 32; i += 8)
        tile[ty+i][tx] = src[(size_t)(kb+ty+i)*N + nb+tx];
    __syncthreads();
    #pragma unroll
    for (int i = 0; i < 32; i += 8)
        dst[(size_t)(nb+ty+i)*K + kb+tx] = tf32r(tile[tx][ty+i]);
}

// ---------------------------------------------------------------------------
// node projection: exact fp32, 8 rows/block (320 blocks)
// ---------------------------------------------------------------------------
__global__ void node_proj_kernel(const float* __restrict__ node,
                                 const float* __restrict__ Wi,
                                 const float* __restrict__ bi,
                                 float* __restrict__ nout)
{
    __shared__ float4 sa[8*96];
    const int r0 = blockIdx.x * 8;
    const float4* node4 = (const float4*)node + (size_t)r0 * 96;
    #pragma unroll
    for (int i = 0; i < 4; i++){ int f = threadIdx.x + i*192; sa[f] = node4[f]; }
    __syncthreads();
    const int c = threadIdx.x;
    float acc[8];
    #pragma unroll
    for (int r = 0; r < 8; r++) acc[r] = 0.f;
    for (int kt = 0; kt < 96; kt++){
        float w0 = Wi[(kt*4+0)*CBIAS + c];
        float w1 = Wi[(kt*4+1)*CBIAS + c];
        float w2 = Wi[(kt*4+2)*CBIAS + c];
        float w3 = Wi[(kt*4+3)*CBIAS + c];
        #pragma unroll
        for (int r = 0; r < 8; r++){
            float4 a = sa[r*96 + kt];
            acc[r] += a.x*w0 + a.y*w1 + a.z*w2 + a.w*w3;
        }
    }
    float bb = bi[c];
    #pragma unroll
    for (int r = 0; r < 8; r++)
        nout[(size_t)(r0+r)*CBIAS + c] = acc[r] + bb;
}

// ---------------------------------------------------------------------------
// build X = concat(edge, self, nbr), tf32-rounded
// ---------------------------------------------------------------------------
__global__ void build_x_kernel(const float* __restrict__ edge,
                               const float* __restrict__ nproj,
                               const int*   __restrict__ eidx,
                               float*       __restrict__ X)
{
    const int f  = blockIdx.x * 256 + threadIdx.x;
    const int m  = f >> 7;
    const int c4 = f & 127;
    const float4* e4 = (const float4*)edge;
    const float4* n4 = (const float4*)nproj;
    float4 v;
    if (c4 < 32){
        v = e4[(size_t)m*32 + c4];
    } else if (c4 < 80){
        int bi_ = m / KNBR;
        v = n4[(size_t)bi_*48 + (c4 - 32)];
    } else {
        int bi_ = m / KNBR;
        int b   = bi_ / N_;
        int j   = eidx[m];
        v = n4[((size_t)b*N_ + j)*48 + (c4 - 80)];
    }
    v.x = tf32r(v.x); v.y = tf32r(v.y); v.z = tf32r(v.z); v.w = tf32r(v.w);
    ((float4*)X)[f] = v;
}

// ---------------------------------------------------------------------------
// TF32 GEMM, mma.sync + ldmatrix. CTA 128x128, 8 warps (2m x 4n),
// warp tile 64x32, BK=32 double-buffered via cp.async.
// A: [m][k] activations. Bt: [n][k] pre-transposed tf32 weights.
// EPI: 0 relu(+round), 1 relu+residual(+round), 2 bias+LayerNorm(COUT)
// ---------------------------------------------------------------------------
enum { EPI_RELU = 0, EPI_RELU_RES = 1, EPI_LN = 2 };

__device__ __forceinline__ void fill_stage(uint32_t base, const float* Ag,
                                           const float* Bg, int kt, int t)
{
    const int koff = kt * 32;
    #pragma unroll
    for (int i = 0; i < 4; i++){
        int id = t + i*256;
        int row = id >> 3, c = id & 7;
        cpasync16(base + (uint32_t)((row*LDA + c*4) << 2),
                  Ag + (size_t)row*HID + koff + c*4);
    }
    #pragma unroll
    for (int i = 0; i < 4; i++){
        int id = t + i*256;
        int row = id >> 3, c = id & 7;
        cpasync16(base + (uint32_t)((TILEF + row*LDA + c*4) << 2),
                  Bg + (size_t)row*HID + koff + c*4);
    }
    CP_COMMIT;
}

template<int EPI>
__global__ __launch_bounds__(256, 2)
void gemm_kernel(const float* __restrict__ A,
                 const float* __restrict__ Bt,
                 const float* __restrict__ bias,
                 const float* Res,                 // may alias Out
                 const float* __restrict__ gamma,
                 const float* __restrict__ beta,
                 float* Out, int ldO)
{
    extern __shared__ float dsm[];
    __shared__ float s_bias[128];
    __shared__ float s_gamma[COUT], s_beta[COUT];
    __shared__ float s_sum[4][128], s_sq[4][128];

    const int t    = threadIdx.x;
    const int wid  = t >> 5, lane = t & 31;
    const int wm   = (wid & 1) * 64;      // 2 m-warps
    const int wni  = wid >> 1;            // 4 n-warps
    const int wn   = wni * 32;
    const int g    = lane >> 2, tig = lane & 3;
    const int m0   = blockIdx.y * 128, n0 = blockIdx.x * 128;

    if (t < 128){
        s_bias[t] = bias[n0 + t];
        if (EPI == EPI_LN){ s_gamma[t] = gamma[t]; s_beta[t] = beta[t]; }
    }

    float acc[4][4][4];
    #pragma unroll
    for (int mt = 0; mt < 4; mt++)
        #pragma unroll
        for (int nt = 0; nt < 4; nt++)
            #pragma unroll
            for (int r = 0; r < 4; r++) acc[mt][nt][r] = 0.f;

    const float* Ag = A  + (size_t)m0 * HID;
    const float* Bg = Bt + (size_t)n0 * HID;
    const uint32_t smU = smem_u32(dsm);

    // ldmatrix per-lane addresses (stage-0 base; add stage/kk byte offsets at use)
    const int rowA = lane & 15, kA = (lane >> 4) * 4;
    uint32_t aBase[4];
    #pragma unroll
    for (int mt = 0; mt < 4; mt++)
        aBase[mt] = smU + (uint32_t)(((wm + mt*16 + rowA)*LDA + kA) << 2);
    const int rowB = (lane & 7) + ((lane >> 4) << 3), kB = ((lane >> 3) & 1) * 4;
    uint32_t bBase[2];
    #pragma unroll
    for (int p = 0; p < 2; p++)
        bBase[p] = smU + (uint32_t)(((TILEF + (wn + p*16 + rowB)*LDA + kB)) << 2);

    fill_stage(smU, Ag, Bg, 0, t);

    for (int kt = 0; kt < 16; kt++){
        const uint32_t stageB = (uint32_t)((kt & 1) * STAGEF) << 2;
        if (kt < 15){
            fill_stage(smU + ((uint32_t)(((kt+1) & 1) * STAGEF) << 2), Ag, Bg, kt+1, t);
            CP_WAIT1;
        } else {
            CP_WAIT0;
        }
        __syncthreads();

        #pragma unroll
        for (int kk = 0; kk < 4; kk++){
            const uint32_t ko = stageB + kk*32;
            unsigned af[4][4], bf[2][4];
            #pragma unroll
            for (int mt = 0; mt < 4; mt++) ldsm4(af[mt], aBase[mt] + ko);
            #pragma unroll
            for (int p = 0; p < 2; p++)    ldsm4(bf[p], bBase[p] + ko);
            #pragma unroll
            for (int mt = 0; mt < 4; mt++)
                #pragma unroll
                for (int nt = 0; nt < 4; nt++)
                    mma_tf32(acc[mt][nt], af[mt], &bf[nt >> 1][(nt & 1)*2]);
        }
        __syncthreads();
    }

    if (EPI != EPI_LN){
        #pragma unroll
        for (int mt = 0; mt < 4; mt++)
            #pragma unroll
            for (int hi = 0; hi < 2; hi++){
                int r = m0 + wm + mt*16 + g + hi*8;
                #pragma unroll
                for (int nt = 0; nt < 4; nt++){
                    int cl = wn + nt*8 + tig*2;
                    float v0 = acc[mt][nt][hi*2    ] + s_bias[cl    ];
                    float v1 = acc[mt][nt][hi*2 + 1] + s_bias[cl + 1];
                    v0 = fmaxf(v0, 0.f); v1 = fmaxf(v1, 0.f);
                    if (EPI == EPI_RELU_RES){
                        float2 x = *(const float2*)(Res + (size_t)r*HID + n0 + cl);
                        v0 += x.x; v1 += x.y;
                    }
                    v0 = tf32r(v0); v1 = tf32r(v1);
                    *(float2*)(Out + (size_t)r*ldO + n0 + cl) = make_float2(v0, v1);
                }
            }
    } else {
        // bias then LayerNorm over 128 cols (n0 == 0)
        #pragma unroll
        for (int mt = 0; mt < 4; mt++)
            #pragma unroll
            for (int nt = 0; nt < 4; nt++){
                int cl = wn + nt*8 + tig*2;
                acc[mt][nt][0] += s_bias[cl];     acc[mt][nt][1] += s_bias[cl+1];
                acc[mt][nt][2] += s_bias[cl];     acc[mt][nt][3] += s_bias[cl+1];
            }
        #pragma unroll
        for (int mt = 0; mt < 4; mt++)
            #pragma unroll
            for (int hi = 0; hi < 2; hi++){
                float s = 0.f, q = 0.f;
                #pragma unroll
                for (int nt = 0; nt < 4; nt++){
                    float v0 = acc[mt][nt][hi*2], v1 = acc[mt][nt][hi*2+1];
                    s += v0 + v1; q += v0*v0 + v1*v1;
                }
                s += __shfl_xor_sync(0xffffffffu, s, 1);
                s += __shfl_xor_sync(0xffffffffu, s, 2);
                q += __shfl_xor_sync(0xffffffffu, q, 1);
                q += __shfl_xor_sync(0xffffffffu, q, 2);
                if (tig == 0){
                    int rl = wm + mt*16 + g + hi*8;
                    s_sum[wni][rl] = s;
                    s_sq [wni][rl] = q;
                }
            }
        __syncthreads();
        #pragma unroll
        for (int mt = 0; mt < 4; mt++)
            #pragma unroll
            for (int hi = 0; hi < 2; hi++){
                int rl = wm + mt*16 + g + hi*8;
                float s = s_sum[0][rl] + s_sum[1][rl] + s_sum[2][rl] + s_sum[3][rl];
                float q = s_sq [0][rl] + s_sq [1][rl] + s_sq [2][rl] + s_sq [3][rl];
                float mean = s * (1.f/128.f);
                float var  = q * (1.f/128.f) - mean*mean;
                float rstd = rsqrtf(var + 1e-5f);
                size_t rbase = (size_t)(m0 + rl) * COUT;
                #pragma unroll
                for (int nt = 0; nt < 4; nt++){
                    int cl = wn + nt*8 + tig*2;
                    float v0 = (acc[mt][nt][hi*2    ] - mean)*rstd*s_gamma[cl    ] + s_beta[cl    ];
                    float v1 = (acc[mt][nt][hi*2 + 1] - mean)*rstd*s_gamma[cl + 1] + s_beta[cl + 1];
                    *(float2*)(Out + rbase + cl) = make_float2(v0, v1);
                }
            }
    }
}

// ---------------------------------------------------------------------------
extern "C" void kernel_launch(void* const* d_in, const int* in_sizes, int n_in,
                              void* d_out, int out_size)
{
    const float* node  = (const float*)d_in[0];
    const float* edge  = (const float*)d_in[1];
    const int*   eidx  = (const int*)  d_in[2];
    const float* Wi    = (const float*)d_in[3];
    const float* bi    = (const float*)d_in[4];
    const float* W1    = (const float*)d_in[5];
    const float* b1    = (const float*)d_in[6];
    const float* W2    = (const float*)d_in[7];
    const float* b2    = (const float*)d_in[8];
    const float* Wf    = (const float*)d_in[9];
    const float* bf    = (const float*)d_in[10];
    const float* gamma = (const float*)d_in[11];
    const float* beta  = (const float*)d_in[12];
    float* out = (float*)d_out;

    void *pn, *px, *ph, *pw1, *pw2, *pwf;
    cudaGetSymbolAddress(&pn,  g_n);
    cudaGetSymbolAddress(&px,  g_X);
    cudaGetSymbolAddress(&ph,  g_H);
    cudaGetSymbolAddress(&pw1, g_W1t);
    cudaGetSymbolAddress(&pw2, g_W2t);
    cudaGetSymbolAddress(&pwf, g_Wft);
    float* gn  = (float*)pn;
    float* gX  = (float*)px;
    float* gH  = (float*)ph;
    float* W1t = (float*)pw1;
    float* W2t = (float*)pw2;
    float* Wft = (float*)pwf;

    cudaFuncSetAttribute(gemm_kernel<EPI_RELU>,     cudaFuncAttributeMaxDynamicSharedMemorySize, DYN_BYTES);
    cudaFuncSetAttribute(gemm_kernel<EPI_RELU_RES>, cudaFuncAttributeMaxDynamicSharedMemorySize, DYN_BYTES);
    cudaFuncSetAttribute(gemm_kernel<EPI_LN>,       cudaFuncAttributeMaxDynamicSharedMemorySize, DYN_BYTES);

    // 0. prep weights: transpose to [N][K] + tf32 round
    dim3 tb(32, 8);
    transpose_round_kernel<<<dim3(HID/32, HID/32), tb>>>(W1, W1t, HID, HID);
    transpose_round_kernel<<<dim3(HID/32, HID/32), tb>>>(W2, W2t, HID, HID);
    transpose_round_kernel<<<dim3(HID/32, COUT/32), tb>>>(Wf, Wft, HID, COUT);

    // 1. node projection (exact fp32)
    node_proj_kernel<<<BN_ROWS/8, 192>>>(node, Wi, bi, gn);

    // 2. build X (tf32-rounded)
    build_x_kernel<<<(M_*128)/256, 256>>>(edge, gn, eidx, gX);

    // 3. H = relu(X @ W1 + b1)
    dim3 grid12(HID/128, M_/128);
    gemm_kernel<EPI_RELU><<<grid12, 256, DYN_BYTES>>>(gX, W1t, b1, nullptr, nullptr, nullptr, gH, HID);

    // 4. X <- relu(H @ W2 + b2) + X  (in-place residual)
    gemm_kernel<EPI_RELU_RES><<<grid12, 256, DYN_BYTES>>>(gH, W2t, b2, gX, nullptr, nullptr, gX, HID);

    // 5. out = LayerNorm((H2+X) @ Wf + bf)
    dim3 grid3(1, M_/128);
    gemm_kernel<EPI_LN><<<grid3, 256, DYN_BYTES>>>(gX, Wft, bf, nullptr, gamma, beta, out, COUT);
}